// round 11
// baseline (speedup 1.0000x reference)
#include <cuda_runtime.h>
#include <cuda_bf16.h>
#include <cuda_fp8.h>
#include <cuda_fp16.h>
#include <math.h>

// Problem constants
#define NQ      6400
#define CDIM    128
#define SCAM    6
#define MPIX    2816     // 32*88
#define HEADS   4
#define POINTS  20
#define HSZ     32
#define WSZ     88
#define DHEAD   32
#define DANCH   4
#define OFF_W   160      // HEADS*POINTS*2
#define ATTN_W  80       // HEADS*POINTS
#define NCOMB   240      // OFF_W + ATTN_W

#define TM      64       // rows per GEMM block

// Scratch (device globals -- no allocation allowed)
__device__ float         g_off[NQ * OFF_W];              // sampling offsets, already /norm
__device__ float         g_aw [NQ * ATTN_W];             // softmaxed attention weights
__device__ unsigned char g_val[SCAM * MPIX * CDIM];      // projected value, (s,pix,c) fp8 e4m3

// Aux stream for A||B overlap -- created once in a static initializer.
namespace {
struct AuxStream {
    cudaStream_t s;
    cudaEvent_t evFork, evJoin;
    AuxStream() {
        cudaStreamCreateWithFlags(&s, cudaStreamNonBlocking);
        cudaEventCreateWithFlags(&evFork, cudaEventDisableTiming);
        cudaEventCreateWithFlags(&evJoin, cudaEventDisableTiming);
    }
};
AuxStream g_aux;
}

// ---------------------------------------------------------------------------
// Kernel A (unchanged): q = query+query_pos; [offsets | attn logits]
// ---------------------------------------------------------------------------
__global__ void k_proj_off_attn_t(const float* __restrict__ query,
                                  const float* __restrict__ qpos,
                                  const float* __restrict__ Woff,
                                  const float* __restrict__ boff,
                                  const float* __restrict__ Wattn,
                                  const float* __restrict__ battn) {
    extern __shared__ float smem[];
    float* sW = smem;                 // [128][240]
    float* sA = smem + 128 * NCOMB;   // [64][128]

    const int n0  = blockIdx.x * TM;
    const int tid = threadIdx.x;

    for (int idx = tid; idx < 128 * NCOMB; idx += 256) {
        const int k = idx / NCOMB, n = idx - k * NCOMB;
        sW[idx] = (n < OFF_W) ? Woff[k * OFF_W + n] : Wattn[k * ATTN_W + (n - OFF_W)];
    }
    for (int idx = tid; idx < TM * 128; idx += 256) {
        const int g = n0 * CDIM + idx;
        sA[idx] = query[g] + qpos[g];
    }
    __syncthreads();

    const int ty = tid >> 4;   // rows ty*4..ty*4+3
    const int tx = tid & 15;   // cols tx + 16*j

    float acc[4][15];
    #pragma unroll
    for (int i = 0; i < 4; i++)
        #pragma unroll
        for (int j = 0; j < 15; j++) acc[i][j] = 0.f;

    #pragma unroll 4
    for (int k = 0; k < 128; k++) {
        float a[4];
        #pragma unroll
        for (int i = 0; i < 4; i++) a[i] = sA[(ty * 4 + i) * 128 + k];
        #pragma unroll
        for (int j = 0; j < 15; j++) {
            const float w = sW[k * NCOMB + tx + 16 * j];
            #pragma unroll
            for (int i = 0; i < 4; i++) acc[i][j] = fmaf(a[i], w, acc[i][j]);
        }
    }
    __syncthreads();

    #pragma unroll
    for (int i = 0; i < 4; i++)
        #pragma unroll
        for (int j = 0; j < 15; j++)
            sW[(ty * 4 + i) * NCOMB + tx + 16 * j] = acc[i][j];
    __syncthreads();

    for (int idx = tid; idx < TM * OFF_W; idx += 256) {
        const int r = idx / OFF_W, t = idx - r * OFF_W;
        const float v = sW[r * NCOMB + t] + boff[t];
        g_off[(n0 + r) * OFF_W + t] = v * ((t & 1) ? (1.f / 32.f) : (1.f / 88.f));
    }
    {
        const int r = tid >> 2, h = tid & 3;
        float lg[POINTS];
        float mx = -1e30f;
        #pragma unroll
        for (int p = 0; p < POINTS; p++) {
            lg[p] = sW[r * NCOMB + OFF_W + h * POINTS + p] + battn[h * POINTS + p];
            mx = fmaxf(mx, lg[p]);
        }
        float sum = 0.f;
        #pragma unroll
        for (int p = 0; p < POINTS; p++) { lg[p] = __expf(lg[p] - mx); sum += lg[p]; }
        const float inv = 1.f / sum;
        #pragma unroll
        for (int p = 0; p < POINTS; p++)
            g_aw[(n0 + r) * ATTN_W + h * POINTS + p] = lg[p] * inv;
    }
}

// ---------------------------------------------------------------------------
// Kernel B (unchanged, col-split): val = value @ Wv + bv -> fp8 e4m3.
// ---------------------------------------------------------------------------
__global__ void k_proj_val_t(const float* __restrict__ value,
                             const float* __restrict__ Wv,
                             const float* __restrict__ bv) {
    extern __shared__ float smem[];
    float* sW = smem;                 // [128][64]
    float* sA = smem + 128 * 64;      // [64][128]

    const int bx  = blockIdx.x;
    const int r0  = (bx >> 1) * TM;   // row tile base
    const int ch  = (bx & 1) * 64;    // column half base
    const int tid = threadIdx.x;

    for (int idx = tid; idx < 128 * 16; idx += 256) {
        const int k = idx >> 4, c4 = idx & 15;
        reinterpret_cast<float4*>(sW)[idx] =
            *reinterpret_cast<const float4*>(&Wv[k * 128 + ch + c4 * 4]);
    }
    for (int idx = tid; idx < TM * 128 / 4; idx += 256)
        reinterpret_cast<float4*>(sA)[idx] =
            reinterpret_cast<const float4*>(value + (size_t)r0 * CDIM)[idx];
    __syncthreads();

    const int ty = tid >> 4;
    const int tx = tid & 15;

    float acc[4][4];
    #pragma unroll
    for (int i = 0; i < 4; i++)
        #pragma unroll
        for (int j = 0; j < 4; j++) acc[i][j] = 0.f;

    for (int k4 = 0; k4 < 128; k4 += 4) {
        float4 av[4];
        #pragma unroll
        for (int i = 0; i < 4; i++)
            av[i] = *reinterpret_cast<const float4*>(&sA[(ty * 4 + i) * 128 + k4]);
        #pragma unroll
        for (int kk = 0; kk < 4; kk++) {
            const float4 w = *reinterpret_cast<const float4*>(&sW[(k4 + kk) * 64 + tx * 4]);
            #pragma unroll
            for (int i = 0; i < 4; i++) {
                const float a = (&av[i].x)[kk];
                acc[i][0] = fmaf(a, w.x, acc[i][0]);
                acc[i][1] = fmaf(a, w.y, acc[i][1]);
                acc[i][2] = fmaf(a, w.z, acc[i][2]);
                acc[i][3] = fmaf(a, w.w, acc[i][3]);
            }
        }
    }

    const float4 b = *reinterpret_cast<const float4*>(&bv[ch + tx * 4]);
    #pragma unroll
    for (int i = 0; i < 4; i++) {
        const int row = r0 + ty * 4 + i;
        const __nv_fp8x2_storage_t p0 = __nv_cvt_float2_to_fp8x2(
            make_float2(acc[i][0] + b.x, acc[i][1] + b.y), __NV_SATFINITE, __NV_E4M3);
        const __nv_fp8x2_storage_t p1 = __nv_cvt_float2_to_fp8x2(
            make_float2(acc[i][2] + b.z, acc[i][3] + b.w), __NV_SATFINITE, __NV_E4M3);
        const unsigned u = (unsigned)p0 | ((unsigned)p1 << 16);
        *reinterpret_cast<unsigned*>(&g_val[(size_t)row * CDIM + ch + tx * 4]) = u;
    }
}

// ---------------------------------------------------------------------------
// Kernel C (FUSED): bilinear sampling + output projection + residual.
// Sampling identical to R10 (staged branch-free gathers, half2 accumulation).
// Epilogue: reduced slots -> smem, then split-k matvec with Wout:
//   thread t: channel group cg = t>>2 (float4 cols), k-range kr = t&3 (32 k);
//   shfl-xor(1,2) combines k-ranges; kr==0 lanes write out + bout + query.
// Wout (64KB) stays L1-resident across the ~43 blocks/SM.
// ---------------------------------------------------------------------------
__global__ void k_sample_out(const float* __restrict__ refpts,   // (S,1,N,4,2)
                             const int* __restrict__ bmask,      // (S,1,N,4) 4-byte flags
                             const float* __restrict__ query,
                             const float* __restrict__ Wout,
                             const float* __restrict__ bout,
                             float* __restrict__ out) {
    const int n      = blockIdx.x;
    const int t      = threadIdx.x;
    const int h      = t >> 5;
    const int lane   = t & 31;
    const int chgrp  = lane & 1;         // 16-channel group
    const int corner = (lane >> 1) & 3;  // bilinear corner
    const int dx     = corner & 1, dy = corner >> 1;
    const int pt     = (lane >> 3) & 3;  // point slot; p = 4*i + pt, anchor d = pt

    __shared__ float sOff[OFF_W];
    __shared__ float sAw[ATTN_W];
    __shared__ float sRef[SCAM * 8];
    __shared__ int   sAct[SCAM];
    __shared__ int   sCnt;
    __shared__ float sSlot[CDIM];

    for (int i = t; i < OFF_W; i += 128)  sOff[i] = g_off[n * OFF_W + i];
    for (int i = t; i < ATTN_W; i += 128) sAw[i]  = g_aw[n * ATTN_W + i];
    for (int i = t; i < SCAM * 8; i += 128) {
        const int s = i >> 3, e = i & 7;
        sRef[i] = refpts[((size_t)s * NQ + n) * 8 + e];
    }
    if (t == 0) {
        int cnt = 0;
        #pragma unroll
        for (int s = 0; s < SCAM; s++) {
            const int4 mw = *reinterpret_cast<const int4*>(bmask + ((size_t)s * NQ + n) * DANCH);
            if (mw.x | mw.y | mw.z | mw.w) sAct[cnt++] = s;
        }
        sCnt = cnt;
    }
    __syncthreads();

    // hoist this lane's 5 points (p = 4i + pt): offsets and attention weights
    float ox[5], oy[5], wp[5];
    #pragma unroll
    for (int i = 0; i < 5; i++) {
        const int p = 4 * i + pt;
        ox[i] = sOff[h * 40 + p * 2 + 0];
        oy[i] = sOff[h * 40 + p * 2 + 1];
        wp[i] = sAw[h * POINTS + p];
    }

    __half2 hacc[8];
    #pragma unroll
    for (int q = 0; q < 8; q++) hacc[q] = __half2half2(__ushort_as_half(0));

    const int cnt = sCnt;
    for (int j = 0; j < cnt; j++) {
        const int s = sAct[j];
        const unsigned char* __restrict__ imgb =
            g_val + (size_t)s * MPIX * CDIM + h * DHEAD + chgrp * 16;
        const float fx = sRef[s * 8 + pt * 2 + 0];
        const float fy = sRef[s * 8 + pt * 2 + 1];

        // stage 1: coords, weights, clamped offsets (branch-free)
        float wcs[5];
        int   offs[5];
        #pragma unroll
        for (int i = 0; i < 5; i++) {
            const float x = (fx + ox[i]) * 88.f - 0.5f;
            const float y = (fy + oy[i]) * 32.f - 0.5f;
            const float x0f = floorf(x), y0f = floorf(y);
            const float wx = x - x0f, wy = y - y0f;
            const int xx = (int)x0f + dx;
            const int yy = (int)y0f + dy;
            const bool valid = ((unsigned)xx < (unsigned)WSZ) & ((unsigned)yy < (unsigned)HSZ);
            const float wc = (dx ? wx : 1.f - wx) * (dy ? wy : 1.f - wy) * wp[i];
            wcs[i] = valid ? wc : 0.f;
            const int xc = min(max(xx, 0), WSZ - 1);
            const int yc = min(max(yy, 0), HSZ - 1);
            offs[i] = (yc * WSZ + xc) * CDIM;
        }

        // stage 2: issue all 5 gathers (MLP = 5)
        uint4 raw[5];
        #pragma unroll
        for (int i = 0; i < 5; i++)
            raw[i] = *reinterpret_cast<const uint4*>(imgb + offs[i]);

        // stage 3: decode + accumulate in half2
        #pragma unroll
        for (int i = 0; i < 5; i++) {
            const __half2 wch = __float2half2_rn(wcs[i]);
            const unsigned rw[4] = {raw[i].x, raw[i].y, raw[i].z, raw[i].w};
            #pragma unroll
            for (int q = 0; q < 4; q++) {
                const __half2_raw lor = __nv_cvt_fp8x2_to_halfraw2(
                    (__nv_fp8x2_storage_t)(rw[q] & 0xffffu), __NV_E4M3);
                const __half2_raw hir = __nv_cvt_fp8x2_to_halfraw2(
                    (__nv_fp8x2_storage_t)(rw[q] >> 16), __NV_E4M3);
                hacc[q * 2 + 0] = __hfma2(wch, *reinterpret_cast<const __half2*>(&lor),
                                          hacc[q * 2 + 0]);
                hacc[q * 2 + 1] = __hfma2(wch, *reinterpret_cast<const __half2*>(&hir),
                                          hacc[q * 2 + 1]);
            }
        }
    }

    // single flush to fp32
    float acc[16];
    #pragma unroll
    for (int q = 0; q < 8; q++) {
        const float2 f = __half22float2(hacc[q]);
        acc[q * 2 + 0] = f.x;
        acc[q * 2 + 1] = f.y;
    }

    // reduce over corners (xor 2, 4) and point slots (xor 8, 16)
    #pragma unroll
    for (int m = 2; m <= 16; m <<= 1)
        #pragma unroll
        for (int i = 0; i < 16; i++)
            acc[i] += __shfl_xor_sync(0xffffffffu, acc[i], m);

    // stash reduced slots (with camera-count divide) to smem
    if (lane < 2) {
        const float inv = 1.f / fmaxf((float)cnt, 1.0f);
        #pragma unroll
        for (int q = 0; q < 16; q++)
            sSlot[h * DHEAD + chgrp * 16 + q] = acc[q] * inv;
    }
    __syncthreads();

    // fused output projection: out[n][c] = sum_k sSlot[k]*Wout[k][c] + bout[c] + query[n][c]
    const int cg = t >> 2;     // channel group: columns cg*4..cg*4+3
    const int kr = t & 3;      // k-range: kr*32..kr*32+31
    float4 o = make_float4(0.f, 0.f, 0.f, 0.f);
    #pragma unroll 8
    for (int k = kr * 32; k < kr * 32 + 32; k++) {
        const float a = sSlot[k];
        const float4 w = *reinterpret_cast<const float4*>(&Wout[k * CDIM + cg * 4]);
        o.x = fmaf(a, w.x, o.x);
        o.y = fmaf(a, w.y, o.y);
        o.z = fmaf(a, w.z, o.z);
        o.w = fmaf(a, w.w, o.w);
    }
    #pragma unroll
    for (int m = 1; m <= 2; m <<= 1) {
        o.x += __shfl_xor_sync(0xffffffffu, o.x, m);
        o.y += __shfl_xor_sync(0xffffffffu, o.y, m);
        o.z += __shfl_xor_sync(0xffffffffu, o.z, m);
        o.w += __shfl_xor_sync(0xffffffffu, o.w, m);
    }
    if (kr == 0) {
        const float4 b = *reinterpret_cast<const float4*>(&bout[cg * 4]);
        const float4 q = *reinterpret_cast<const float4*>(&query[(size_t)n * CDIM + cg * 4]);
        *reinterpret_cast<float4*>(&out[(size_t)n * CDIM + cg * 4]) =
            make_float4(o.x + b.x + q.x, o.y + b.y + q.y,
                        o.z + b.z + q.z, o.w + b.w + q.w);
    }
}

// ---------------------------------------------------------------------------
// Launch. Input order per setup_inputs:
// 0 query, 1 key (unused), 2 value, 3 query_pos, 4 reference_points_cam,
// 5 bev_mask, 6 spatial_shapes, 7 level_start_index, 8 Wv, 9 bv, 10 Woff,
// 11 boff, 12 Wattn, 13 battn, 14 Wout, 15 bout
// ---------------------------------------------------------------------------
extern "C" void kernel_launch(void* const* d_in, const int* in_sizes, int n_in,
                              void* d_out, int out_size) {
    const float* query = (const float*)d_in[0];
    const float* value = (const float*)d_in[2];
    const float* qpos  = (const float*)d_in[3];
    const float* refp  = (const float*)d_in[4];
    const int*   bmask = (const int*)d_in[5];
    const float* Wv    = (const float*)d_in[8];
    const float* bv    = (const float*)d_in[9];
    const float* Woff  = (const float*)d_in[10];
    const float* boff  = (const float*)d_in[11];
    const float* Wattn = (const float*)d_in[12];
    const float* battn = (const float*)d_in[13];
    const float* Wout  = (const float*)d_in[14];
    const float* bout  = (const float*)d_in[15];
    float* out = (float*)d_out;

    const int smemA = (128 * NCOMB + TM * 128) * sizeof(float);   // 155648
    const int smemH = (128 * 64 + TM * 128) * sizeof(float);      // 65536

    cudaFuncSetAttribute(k_proj_off_attn_t, cudaFuncAttributeMaxDynamicSharedMemorySize, smemA);
    cudaFuncSetAttribute(k_proj_val_t,      cudaFuncAttributeMaxDynamicSharedMemorySize, smemH);

    // Fork: A on the aux stream, B on the main stream; join before sampling.
    cudaEventRecord(g_aux.evFork, 0);
    cudaStreamWaitEvent(g_aux.s, g_aux.evFork, 0);
    k_proj_off_attn_t<<<NQ / TM, 256, smemA, g_aux.s>>>(query, qpos, Woff, boff, Wattn, battn);
    cudaEventRecord(g_aux.evJoin, g_aux.s);

    k_proj_val_t<<<(SCAM * MPIX / TM) * 2, 256, smemH>>>(value, Wv, bv);
    cudaStreamWaitEvent(0, g_aux.evJoin, 0);

    k_sample_out<<<NQ, CDIM>>>(refp, bmask, query, Wout, bout, out);
}

// round 12
// speedup vs baseline: 1.5774x; 1.5774x over previous
#include <cuda_runtime.h>
#include <cuda_bf16.h>
#include <cuda_fp8.h>
#include <cuda_fp16.h>
#include <math.h>

// Problem constants
#define NQ      6400
#define CDIM    128
#define SCAM    6
#define MPIX    2816     // 32*88
#define HEADS   4
#define POINTS  20
#define HSZ     32
#define WSZ     88
#define DHEAD   32
#define DANCH   4
#define OFF_W   160      // HEADS*POINTS*2
#define ATTN_W  80       // HEADS*POINTS
#define NCOMB   240      // OFF_W + ATTN_W

#define TM      64       // rows per GEMM block
#define ACOLS   80       // columns per kernel-A part (3 parts: 80+80+80)

// Scratch (device globals -- no allocation allowed)
__device__ float         g_off[NQ * OFF_W];              // sampling offsets, already /norm
__device__ float         g_aw [NQ * ATTN_W];             // softmaxed attention weights
__device__ unsigned char g_val[SCAM * MPIX * CDIM];      // projected value, (s,pix,c) fp8 e4m3
__device__ float         g_slots[NQ * CDIM];             // per-query accumulated slots

// Aux stream for A||B overlap -- created once in a static initializer.
namespace {
struct AuxStream {
    cudaStream_t s;
    cudaEvent_t evFork, evJoin;
    AuxStream() {
        cudaStreamCreateWithFlags(&s, cudaStreamNonBlocking);
        cudaEventCreateWithFlags(&evFork, cudaEventDisableTiming);
        cudaEventCreateWithFlags(&evJoin, cudaEventDisableTiming);
    }
};
AuxStream g_aux;
}

// ---------------------------------------------------------------------------
// Kernel A (3-way col-split): q = query+query_pos; part 0/1 -> offset cols
// [part*80, part*80+80); part 2 -> the 80 attn logit cols (+softmax).
// 256 threads, 64 rows x 80 cols, micro-tile 4 rows x 5 cols.
// smem: sW 128x80 (40KB) + sA 64x128 (32KB) = 72KB -> 3 CTAs/SM. grid 300.
// ---------------------------------------------------------------------------
__global__ void k_proj_off_attn_t(const float* __restrict__ query,
                                  const float* __restrict__ qpos,
                                  const float* __restrict__ Woff,
                                  const float* __restrict__ boff,
                                  const float* __restrict__ Wattn,
                                  const float* __restrict__ battn) {
    extern __shared__ float smem[];
    float* sW = smem;                 // [128][80]
    float* sA = smem + 128 * ACOLS;   // [64][128]

    const int bx   = blockIdx.x;
    const int n0   = (bx / 3) * TM;
    const int part = bx % 3;          // 0,1: offsets; 2: attn
    const int tid  = threadIdx.x;

    // load weights: 80 floats/row = 20 float4
    if (part < 2) {
        for (int idx = tid; idx < 128 * 20; idx += 256) {
            const int k = idx / 20, c4 = idx % 20;
            reinterpret_cast<float4*>(sW)[idx] =
                *reinterpret_cast<const float4*>(&Woff[k * OFF_W + part * ACOLS + c4 * 4]);
        }
    } else {
        for (int idx = tid; idx < 128 * 20; idx += 256)
            reinterpret_cast<float4*>(sW)[idx] = reinterpret_cast<const float4*>(Wattn)[idx];
    }
    for (int idx = tid; idx < TM * 128 / 4; idx += 256) {
        const float4 q4 = reinterpret_cast<const float4*>(query + (size_t)n0 * CDIM)[idx];
        const float4 p4 = reinterpret_cast<const float4*>(qpos + (size_t)n0 * CDIM)[idx];
        reinterpret_cast<float4*>(sA)[idx] =
            make_float4(q4.x + p4.x, q4.y + p4.y, q4.z + p4.z, q4.w + p4.w);
    }
    __syncthreads();

    const int ty = tid >> 4;   // rows ty*4..ty*4+3
    const int tx = tid & 15;   // cols tx + 16*j, j=0..4

    float acc[4][5];
    #pragma unroll
    for (int i = 0; i < 4; i++)
        #pragma unroll
        for (int j = 0; j < 5; j++) acc[i][j] = 0.f;

    #pragma unroll 4
    for (int k = 0; k < 128; k++) {
        float a[4];
        #pragma unroll
        for (int i = 0; i < 4; i++) a[i] = sA[(ty * 4 + i) * 128 + k];
        #pragma unroll
        for (int j = 0; j < 5; j++) {
            const float w = sW[k * ACOLS + tx + 16 * j];
            #pragma unroll
            for (int i = 0; i < 4; i++) acc[i][j] = fmaf(a[i], w, acc[i][j]);
        }
    }

    if (part < 2) {
        // offsets epilogue straight from registers: bias + /norm
        #pragma unroll
        for (int i = 0; i < 4; i++) {
            const int r = n0 + ty * 4 + i;
            #pragma unroll
            for (int j = 0; j < 5; j++) {
                const int c = tx + 16 * j;              // 0..79 within part
                const int t = part * ACOLS + c;         // global offset col
                const float v = acc[i][j] + boff[t];
                g_off[(size_t)r * OFF_W + t] = v * ((t & 1) ? (1.f / 32.f) : (1.f / 88.f));
            }
        }
    } else {
        // attn: stage logits to smem (reuse sW: 64x80 fits in 128x80), softmax
        __syncthreads();
        #pragma unroll
        for (int i = 0; i < 4; i++)
            #pragma unroll
            for (int j = 0; j < 5; j++)
                sW[(ty * 4 + i) * ACOLS + tx + 16 * j] = acc[i][j];
        __syncthreads();

        const int r = tid >> 2, h = tid & 3;   // 64 rows x 4 heads
        float lg[POINTS];
        float mx = -1e30f;
        #pragma unroll
        for (int p = 0; p < POINTS; p++) {
            lg[p] = sW[r * ACOLS + h * POINTS + p] + battn[h * POINTS + p];
            mx = fmaxf(mx, lg[p]);
        }
        float sum = 0.f;
        #pragma unroll
        for (int p = 0; p < POINTS; p++) { lg[p] = __expf(lg[p] - mx); sum += lg[p]; }
        const float inv = 1.f / sum;
        #pragma unroll
        for (int p = 0; p < POINTS; p++)
            g_aw[(size_t)(n0 + r) * ATTN_W + h * POINTS + p] = lg[p] * inv;
    }
}

// ---------------------------------------------------------------------------
// Kernel B (unchanged, col-split): val = value @ Wv + bv -> fp8 e4m3.
// ---------------------------------------------------------------------------
__global__ void k_proj_val_t(const float* __restrict__ value,
                             const float* __restrict__ Wv,
                             const float* __restrict__ bv) {
    extern __shared__ float smem[];
    float* sW = smem;                 // [128][64]
    float* sA = smem + 128 * 64;      // [64][128]

    const int bx  = blockIdx.x;
    const int r0  = (bx >> 1) * TM;   // row tile base
    const int ch  = (bx & 1) * 64;    // column half base
    const int tid = threadIdx.x;

    for (int idx = tid; idx < 128 * 16; idx += 256) {
        const int k = idx >> 4, c4 = idx & 15;
        reinterpret_cast<float4*>(sW)[idx] =
            *reinterpret_cast<const float4*>(&Wv[k * 128 + ch + c4 * 4]);
    }
    for (int idx = tid; idx < TM * 128 / 4; idx += 256)
        reinterpret_cast<float4*>(sA)[idx] =
            reinterpret_cast<const float4*>(value + (size_t)r0 * CDIM)[idx];
    __syncthreads();

    const int ty = tid >> 4;
    const int tx = tid & 15;

    float acc[4][4];
    #pragma unroll
    for (int i = 0; i < 4; i++)
        #pragma unroll
        for (int j = 0; j < 4; j++) acc[i][j] = 0.f;

    for (int k4 = 0; k4 < 128; k4 += 4) {
        float4 av[4];
        #pragma unroll
        for (int i = 0; i < 4; i++)
            av[i] = *reinterpret_cast<const float4*>(&sA[(ty * 4 + i) * 128 + k4]);
        #pragma unroll
        for (int kk = 0; kk < 4; kk++) {
            const float4 w = *reinterpret_cast<const float4*>(&sW[(k4 + kk) * 64 + tx * 4]);
            #pragma unroll
            for (int i = 0; i < 4; i++) {
                const float a = (&av[i].x)[kk];
                acc[i][0] = fmaf(a, w.x, acc[i][0]);
                acc[i][1] = fmaf(a, w.y, acc[i][1]);
                acc[i][2] = fmaf(a, w.z, acc[i][2]);
                acc[i][3] = fmaf(a, w.w, acc[i][3]);
            }
        }
    }

    const float4 b = *reinterpret_cast<const float4*>(&bv[ch + tx * 4]);
    #pragma unroll
    for (int i = 0; i < 4; i++) {
        const int row = r0 + ty * 4 + i;
        const __nv_fp8x2_storage_t p0 = __nv_cvt_float2_to_fp8x2(
            make_float2(acc[i][0] + b.x, acc[i][1] + b.y), __NV_SATFINITE, __NV_E4M3);
        const __nv_fp8x2_storage_t p1 = __nv_cvt_float2_to_fp8x2(
            make_float2(acc[i][2] + b.z, acc[i][3] + b.w), __NV_SATFINITE, __NV_E4M3);
        const unsigned u = (unsigned)p0 | ((unsigned)p1 << 16);
        *reinterpret_cast<unsigned*>(&g_val[(size_t)row * CDIM + ch + tx * 4]) = u;
    }
}

// ---------------------------------------------------------------------------
// Kernel C (reverted to R10): bilinear sampling, staged branch-free gathers,
// half2 accumulation across cameras, butterfly reduction.
// ---------------------------------------------------------------------------
__global__ void k_sample(const float* __restrict__ refpts,   // (S,1,N,4,2)
                         const int* __restrict__ bmask) {    // (S,1,N,4) 4-byte flags
    const int n      = blockIdx.x;
    const int t      = threadIdx.x;
    const int h      = t >> 5;
    const int lane   = t & 31;
    const int chgrp  = lane & 1;         // 16-channel group
    const int corner = (lane >> 1) & 3;  // bilinear corner
    const int dx     = corner & 1, dy = corner >> 1;
    const int pt     = (lane >> 3) & 3;  // point slot; p = 4*i + pt, anchor d = pt

    __shared__ float sOff[OFF_W];
    __shared__ float sAw[ATTN_W];
    __shared__ float sRef[SCAM * 8];
    __shared__ int   sAct[SCAM];
    __shared__ int   sCnt;

    for (int i = t; i < OFF_W; i += 128)  sOff[i] = g_off[n * OFF_W + i];
    for (int i = t; i < ATTN_W; i += 128) sAw[i]  = g_aw[n * ATTN_W + i];
    for (int i = t; i < SCAM * 8; i += 128) {
        const int s = i >> 3, e = i & 7;
        sRef[i] = refpts[((size_t)s * NQ + n) * 8 + e];
    }
    if (t == 0) {
        int cnt = 0;
        #pragma unroll
        for (int s = 0; s < SCAM; s++) {
            const int4 mw = *reinterpret_cast<const int4*>(bmask + ((size_t)s * NQ + n) * DANCH);
            if (mw.x | mw.y | mw.z | mw.w) sAct[cnt++] = s;
        }
        sCnt = cnt;
    }
    __syncthreads();

    float ox[5], oy[5], wp[5];
    #pragma unroll
    for (int i = 0; i < 5; i++) {
        const int p = 4 * i + pt;
        ox[i] = sOff[h * 40 + p * 2 + 0];
        oy[i] = sOff[h * 40 + p * 2 + 1];
        wp[i] = sAw[h * POINTS + p];
    }

    __half2 hacc[8];
    #pragma unroll
    for (int q = 0; q < 8; q++) hacc[q] = __half2half2(__ushort_as_half(0));

    const int cnt = sCnt;
    for (int j = 0; j < cnt; j++) {
        const int s = sAct[j];
        const unsigned char* __restrict__ imgb =
            g_val + (size_t)s * MPIX * CDIM + h * DHEAD + chgrp * 16;
        const float fx = sRef[s * 8 + pt * 2 + 0];
        const float fy = sRef[s * 8 + pt * 2 + 1];

        float wcs[5];
        int   offs[5];
        #pragma unroll
        for (int i = 0; i < 5; i++) {
            const float x = (fx + ox[i]) * 88.f - 0.5f;
            const float y = (fy + oy[i]) * 32.f - 0.5f;
            const float x0f = floorf(x), y0f = floorf(y);
            const float wx = x - x0f, wy = y - y0f;
            const int xx = (int)x0f + dx;
            const int yy = (int)y0f + dy;
            const bool valid = ((unsigned)xx < (unsigned)WSZ) & ((unsigned)yy < (unsigned)HSZ);
            const float wc = (dx ? wx : 1.f - wx) * (dy ? wy : 1.f - wy) * wp[i];
            wcs[i] = valid ? wc : 0.f;
            const int xc = min(max(xx, 0), WSZ - 1);
            const int yc = min(max(yy, 0), HSZ - 1);
            offs[i] = (yc * WSZ + xc) * CDIM;
        }

        uint4 raw[5];
        #pragma unroll
        for (int i = 0; i < 5; i++)
            raw[i] = *reinterpret_cast<const uint4*>(imgb + offs[i]);

        #pragma unroll
        for (int i = 0; i < 5; i++) {
            const __half2 wch = __float2half2_rn(wcs[i]);
            const unsigned rw[4] = {raw[i].x, raw[i].y, raw[i].z, raw[i].w};
            #pragma unroll
            for (int q = 0; q < 4; q++) {
                const __half2_raw lor = __nv_cvt_fp8x2_to_halfraw2(
                    (__nv_fp8x2_storage_t)(rw[q] & 0xffffu), __NV_E4M3);
                const __half2_raw hir = __nv_cvt_fp8x2_to_halfraw2(
                    (__nv_fp8x2_storage_t)(rw[q] >> 16), __NV_E4M3);
                hacc[q * 2 + 0] = __hfma2(wch, *reinterpret_cast<const __half2*>(&lor),
                                          hacc[q * 2 + 0]);
                hacc[q * 2 + 1] = __hfma2(wch, *reinterpret_cast<const __half2*>(&hir),
                                          hacc[q * 2 + 1]);
            }
        }
    }

    float acc[16];
    #pragma unroll
    for (int q = 0; q < 8; q++) {
        const float2 f = __half22float2(hacc[q]);
        acc[q * 2 + 0] = f.x;
        acc[q * 2 + 1] = f.y;
    }

    #pragma unroll
    for (int m = 2; m <= 16; m <<= 1)
        #pragma unroll
        for (int i = 0; i < 16; i++)
            acc[i] += __shfl_xor_sync(0xffffffffu, acc[i], m);

    if (lane < 2) {
        const float inv = 1.f / fmaxf((float)cnt, 1.0f);
        float* dst = g_slots + (size_t)n * CDIM + h * DHEAD + chgrp * 16;
        #pragma unroll
        for (int q = 0; q < 4; q++) {
            float4 o = make_float4(acc[q * 4 + 0] * inv, acc[q * 4 + 1] * inv,
                                   acc[q * 4 + 2] * inv, acc[q * 4 + 3] * inv);
            *reinterpret_cast<float4*>(dst + q * 4) = o;
        }
    }
}

// ---------------------------------------------------------------------------
// Kernel D (reverted to R10, col-split): out = slots @ Wout + bout + residual.
// ---------------------------------------------------------------------------
__global__ void k_out_t(const float* __restrict__ query,
                        const float* __restrict__ Wout,
                        const float* __restrict__ bout,
                        float* __restrict__ out) {
    extern __shared__ float smem[];
    float* sW = smem;                 // [128][64]
    float* sA = smem + 128 * 64;      // [64][128]

    const int bx  = blockIdx.x;
    const int r0  = (bx >> 1) * TM;
    const int ch  = (bx & 1) * 64;
    const int tid = threadIdx.x;

    for (int idx = tid; idx < 128 * 16; idx += 256) {
        const int k = idx >> 4, c4 = idx & 15;
        reinterpret_cast<float4*>(sW)[idx] =
            *reinterpret_cast<const float4*>(&Wout[k * 128 + ch + c4 * 4]);
    }
    for (int idx = tid; idx < TM * 128 / 4; idx += 256)
        reinterpret_cast<float4*>(sA)[idx] =
            reinterpret_cast<const float4*>(g_slots + (size_t)r0 * CDIM)[idx];
    __syncthreads();

    const int ty = tid >> 4;
    const int tx = tid & 15;

    float acc[4][4];
    #pragma unroll
    for (int i = 0; i < 4; i++)
        #pragma unroll
        for (int j = 0; j < 4; j++) acc[i][j] = 0.f;

    for (int k4 = 0; k4 < 128; k4 += 4) {
        float4 av[4];
        #pragma unroll
        for (int i = 0; i < 4; i++)
            av[i] = *reinterpret_cast<const float4*>(&sA[(ty * 4 + i) * 128 + k4]);
        #pragma unroll
        for (int kk = 0; kk < 4; kk++) {
            const float4 w = *reinterpret_cast<const float4*>(&sW[(k4 + kk) * 64 + tx * 4]);
            #pragma unroll
            for (int i = 0; i < 4; i++) {
                const float a = (&av[i].x)[kk];
                acc[i][0] = fmaf(a, w.x, acc[i][0]);
                acc[i][1] = fmaf(a, w.y, acc[i][1]);
                acc[i][2] = fmaf(a, w.z, acc[i][2]);
                acc[i][3] = fmaf(a, w.w, acc[i][3]);
            }
        }
    }

    const float4 b = *reinterpret_cast<const float4*>(&bout[ch + tx * 4]);
    #pragma unroll
    for (int i = 0; i < 4; i++) {
        const int row = r0 + ty * 4 + i;
        const float4 q = *reinterpret_cast<const float4*>(&query[row * CDIM + ch + tx * 4]);
        float4 o = make_float4(acc[i][0] + b.x + q.x, acc[i][1] + b.y + q.y,
                               acc[i][2] + b.z + q.z, acc[i][3] + b.w + q.w);
        *reinterpret_cast<float4*>(&out[row * CDIM + ch + tx * 4]) = o;
    }
}

// ---------------------------------------------------------------------------
// Launch. Input order per setup_inputs:
// 0 query, 1 key (unused), 2 value, 3 query_pos, 4 reference_points_cam,
// 5 bev_mask, 6 spatial_shapes, 7 level_start_index, 8 Wv, 9 bv, 10 Woff,
// 11 boff, 12 Wattn, 13 battn, 14 Wout, 15 bout
// ---------------------------------------------------------------------------
extern "C" void kernel_launch(void* const* d_in, const int* in_sizes, int n_in,
                              void* d_out, int out_size) {
    const float* query = (const float*)d_in[0];
    const float* value = (const float*)d_in[2];
    const float* qpos  = (const float*)d_in[3];
    const float* refp  = (const float*)d_in[4];
    const int*   bmask = (const int*)d_in[5];
    const float* Wv    = (const float*)d_in[8];
    const float* bv    = (const float*)d_in[9];
    const float* Woff  = (const float*)d_in[10];
    const float* boff  = (const float*)d_in[11];
    const float* Wattn = (const float*)d_in[12];
    const float* battn = (const float*)d_in[13];
    const float* Wout  = (const float*)d_in[14];
    const float* bout  = (const float*)d_in[15];
    float* out = (float*)d_out;

    const int smemA = (128 * ACOLS + TM * 128) * sizeof(float);   // 73728
    const int smemH = (128 * 64 + TM * 128) * sizeof(float);      // 65536

    cudaFuncSetAttribute(k_proj_off_attn_t, cudaFuncAttributeMaxDynamicSharedMemorySize, smemA);
    cudaFuncSetAttribute(k_proj_val_t,      cudaFuncAttributeMaxDynamicSharedMemorySize, smemH);
    cudaFuncSetAttribute(k_out_t,           cudaFuncAttributeMaxDynamicSharedMemorySize, smemH);

    // Fork: A on the aux stream, B on the main stream; join before sampling.
    cudaEventRecord(g_aux.evFork, 0);
    cudaStreamWaitEvent(g_aux.s, g_aux.evFork, 0);
    k_proj_off_attn_t<<<(NQ / TM) * 3, 256, smemA, g_aux.s>>>(query, qpos, Woff, boff, Wattn, battn);
    cudaEventRecord(g_aux.evJoin, g_aux.s);

    k_proj_val_t<<<(SCAM * MPIX / TM) * 2, 256, smemH>>>(value, Wv, bv);
    cudaStreamWaitEvent(0, g_aux.evJoin, 0);

    k_sample<<<NQ, CDIM>>>(refp, bmask);
    k_out_t<<<(NQ / TM) * 2, 256, smemH>>>(query, Wout, bout, out);
}